// round 14
// baseline (speedup 1.0000x reference)
#include <cuda_runtime.h>
#include <cuda_fp16.h>
#include <cstdint>

// Problem constants
#define NT_   128      // N*T
#define V_    1024
#define CIN_  256
#define COUT_ 64

// Scratch: theta/phi projections, fp16, row-major [v][64] with k-permuted
// 16-groups => {2t,2t+1,2t+8,2t+9} contiguous: one 8B load per mma fragment.
__device__ __half g_theta[NT_ * V_ * COUT_];
__device__ __half g_phi[NT_ * V_ * COUT_];
// exp(S) scratch, fp16, [NT, V, V] as uint(half2) pairs. Written and re-read
// by the SAME CTA within ~50us => effectively L2-resident (live set ~38MB).
__device__ unsigned g_E[(size_t)NT_ * V_ * V_ / 2];

// ---------------- tf32 mma (proj kernel) ----------------
__device__ __forceinline__ void mma_tf32(float* c,
                                         float a0, float a1, float a2, float a3,
                                         float b0, float b1) {
    asm volatile(
        "mma.sync.aligned.m16n8k8.row.col.f32.tf32.tf32.f32 "
        "{%0,%1,%2,%3},{%4,%5,%6,%7},{%8,%9},{%0,%1,%2,%3};\n"
        : "+f"(c[0]), "+f"(c[1]), "+f"(c[2]), "+f"(c[3])
        : "r"(__float_as_uint(a0)), "r"(__float_as_uint(a1)),
          "r"(__float_as_uint(a2)), "r"(__float_as_uint(a3)),
          "r"(__float_as_uint(b0)), "r"(__float_as_uint(b1)));
}

// ---------------- fp16 mma (adj kernel) ----------------
__device__ __forceinline__ void mma_f16(float* c,
                                        unsigned a0, unsigned a1,
                                        unsigned a2, unsigned a3,
                                        unsigned b0, unsigned b1) {
    asm volatile(
        "mma.sync.aligned.m16n8k16.row.col.f32.f16.f16.f32 "
        "{%0,%1,%2,%3},{%4,%5,%6,%7},{%8,%9},{%0,%1,%2,%3};\n"
        : "+f"(c[0]), "+f"(c[1]), "+f"(c[2]), "+f"(c[3])
        : "r"(a0), "r"(a1), "r"(a2), "r"(a3), "r"(b0), "r"(b1));
}

__device__ __forceinline__ uint32_t smem_u32(const void* p) {
    uint32_t a;
    asm("{ .reg .u64 t; cvta.to.shared.u64 t, %1; cvt.u32.u64 %0, t; }"
        : "=r"(a) : "l"(p));
    return a;
}
__device__ __forceinline__ void cp16s(uint32_t daddr, const void* src) {
    asm volatile("cp.async.cg.shared.global [%0], [%1], 16;\n" :: "r"(daddr), "l"(src));
}
__device__ __forceinline__ void cp_commit() { asm volatile("cp.async.commit_group;\n"); }
__device__ __forceinline__ void cp_wait0() { asm volatile("cp.async.wait_group 0;\n" ::: "memory"); }
__device__ __forceinline__ void cp_wait1() { asm volatile("cp.async.wait_group 1;\n" ::: "memory"); }

// ============================================================================
// Kernel 1: projection (unchanged from R12).
// Block: 128 v-rows x 128 out-cols, 256 thr, 2 CTAs/SM.
// ============================================================================
#define PJ_SR     40
#define PJ_A_SZ   (128 * PJ_SR)
#define PJ_BUF    (2 * PJ_A_SZ)
#define PJ_SMEM_BYTES (2 * PJ_BUF * 4)

__global__ void __launch_bounds__(256, 2) proj_kernel(
    const float* __restrict__ z, const float* __restrict__ tw,
    const float* __restrict__ tb, const float* __restrict__ pw,
    const float* __restrict__ pb)
{
    extern __shared__ float psm[];
    __shared__ float bias_s[128];

    const int tid = threadIdx.x, lane = tid & 31, wid = tid >> 5;
    const int g = lane >> 2, t = lane & 3;
    const int wm = wid & 3, wn = wid >> 2;
    const int nt = blockIdx.y;
    const int vbase = blockIdx.x * 128;

    if (tid < 128) bias_s[tid] = (tid < 64) ? tb[tid] : pb[tid - 64];

    const float* zb = z + (size_t)(nt * V_ + vbase) * CIN_;
    const uint32_t sb = smem_u32(psm);

    auto stage = [&](int c, int b) {
        const uint32_t ab = sb + (uint32_t)(b * PJ_BUF) * 4u;
        const uint32_t bb = ab + (uint32_t)PJ_A_SZ * 4u;
        const int kc = c * 32;
        #pragma unroll
        for (int p = 0; p < 4; p++) {
            int lin = tid + 256 * p;
            int r = lin >> 3, c8 = lin & 7;
            cp16s(ab + (uint32_t)(r * PJ_SR * 4 + c8 * 16),
                  zb + (size_t)r * CIN_ + kc + c8 * 4);
        }
        #pragma unroll
        for (int p = 0; p < 4; p++) {
            int lin = tid + 256 * p;
            int r = lin >> 3, c8 = lin & 7;
            const float* src = (r < 64) ? (tw + (size_t)r * CIN_)
                                        : (pw + (size_t)(r - 64) * CIN_);
            cp16s(bb + (uint32_t)(r * PJ_SR * 4 + c8 * 16), src + kc + c8 * 4);
        }
        cp_commit();
    };

    float acc[2][8][4];
    #pragma unroll
    for (int i = 0; i < 2; i++)
        #pragma unroll
        for (int j = 0; j < 8; j++)
            #pragma unroll
            for (int k = 0; k < 4; k++) acc[i][j][k] = 0.f;

    stage(0, 0);
    for (int c = 0; c < 8; c++) {
        if (c < 7) stage(c + 1, (c + 1) & 1);
        if (c < 7) cp_wait1(); else cp_wait0();
        __syncthreads();
        const float* A = psm + (c & 1) * PJ_BUF;
        const float* B = A + PJ_A_SZ;

        #pragma unroll
        for (int ks = 0; ks < 4; ks++) {
            const int ko = ks * 8 + 2 * t;
            float2 a0[2], a1[2];
            #pragma unroll
            for (int mf = 0; mf < 2; mf++) {
                a0[mf] = *(const float2*)&A[(wm * 32 + mf * 16 + g) * PJ_SR + ko];
                a1[mf] = *(const float2*)&A[(wm * 32 + mf * 16 + 8 + g) * PJ_SR + ko];
            }
            #pragma unroll
            for (int nf = 0; nf < 8; nf++) {
                float2 bf = *(const float2*)&B[(wn * 64 + nf * 8 + g) * PJ_SR + ko];
                #pragma unroll
                for (int mf = 0; mf < 2; mf++)
                    mma_tf32(acc[mf][nf], a0[mf].x, a1[mf].x, a0[mf].y, a1[mf].y,
                             bf.x, bf.y);
            }
        }
        __syncthreads();
    }

    // Epilogue: bias, convert to fp16, store at permuted k positions.
    __half* dst = wn ? g_phi : g_theta;
    #pragma unroll
    for (int mf = 0; mf < 2; mf++) {
        const size_t row0 = (size_t)(nt * V_) + vbase + wm * 32 + mf * 16 + g;
        #pragma unroll
        for (int nf = 0; nf < 8; nf++) {
            int c = nf * 8 + 2 * t;
            float b0 = bias_s[wn * 64 + c], b1 = bias_s[wn * 64 + c + 1];
            __half2 h0 = __floats2half2_rn(acc[mf][nf][0] + b0, acc[mf][nf][1] + b1);
            __half2 h1 = __floats2half2_rn(acc[mf][nf][2] + b0, acc[mf][nf][3] + b1);
            int h2i = (nf >> 1) * 8 + 2 * t + (nf & 1);
            *(__half2*)&dst[row0 * COUT_ + 2 * h2i] = h0;
            *(__half2*)&dst[(row0 + 8) * COUT_ + 2 * h2i] = h1;
        }
    }
}

// ============================================================================
// Kernel 2: fp16-HMMA single-exp softmax-GEMM, E in L2-resident gmem scratch.
// Block: 32 theta rows x 1024 cols, 256 thr. SMEM = phi double-buf only
// (20.5KB) -> 4 CTAs/SM = 32 warps. Pass1: mma->exp->E(gmem)+rowsums.
// Pass2: read E (L2 hit), scale, write G.
// ============================================================================
#define BROW_B   160                       // bytes per phi row (128 data + 32 pad)
#define PBUF_B   (64 * BROW_B)             // 10240
#define ADJ_SMEM_BYTES (2 * PBUF_B)        // 20480

__global__ void __launch_bounds__(256, 4) adj_kernel(float* __restrict__ G)
{
    extern __shared__ char Pc[];              // 2 x 64 x BROW_B
    __shared__ float red[128];
    __shared__ float invs[32];

    const int tid = threadIdx.x, lane = tid & 31, wid = tid >> 5;
    const int g = lane >> 2, t = lane & 3;
    const int wm = wid & 1;     // 2 m-warps x 16 rows
    const int wn = wid >> 1;    // 4 n-warps x 16 cols (per 64-col chunk)
    const int nt = blockIdx.x >> 5;
    const int vbase = (blockIdx.x & 31) * 32;

    const __half* th = g_theta + (size_t)(nt * V_ + vbase) * COUT_;
    const __half* ph = g_phi + (size_t)nt * V_ * COUT_;
    unsigned* Eb = g_E + (size_t)(nt * V_ + vbase) * (V_ / 2);   // 32 rows x 512 uints
    const uint32_t pbb = smem_u32(Pc);

    // Theta fragments -> registers (one LDG.64 each, permuted layout).
    uint2 a_lo[4], a_hi[4];
    #pragma unroll
    for (int ks = 0; ks < 4; ks++) {
        a_lo[ks] = *(const uint2*)&th[(size_t)(wm * 16 + g) * COUT_ + ks * 16 + 4 * t];
        a_hi[ks] = *(const uint2*)&th[(size_t)(wm * 16 + 8 + g) * COUT_ + ks * 16 + 4 * t];
    }

    auto stage = [&](int c, int b) {
        const uint32_t dst = pbb + (uint32_t)(b * PBUF_B);
        const __half* src = ph + (size_t)c * 64 * COUT_;
        #pragma unroll
        for (int p = 0; p < 2; p++) {
            int lin = tid + 256 * p;          // 0..511: 64 rows x 8 16B-chunks
            int r = lin >> 3, c8 = lin & 7;
            cp16s(dst + (uint32_t)(r * BROW_B + c8 * 16),
                  src + (size_t)r * COUT_ + c8 * 8);
        }
        cp_commit();
    };

    stage(0, 0);
    float rowsum0 = 0.f, rowsum1 = 0.f;

    // ---------------- PASS 1: mma -> exp -> E(gmem) + rowsums ----------------
    for (int c = 0; c < 16; c++) {
        if (c < 15) stage(c + 1, (c + 1) & 1);
        if (c < 15) cp_wait1(); else cp_wait0();
        __syncthreads();
        const char* B = Pc + (c & 1) * PBUF_B;

        float acc[2][4];
        #pragma unroll
        for (int j = 0; j < 2; j++)
            #pragma unroll
            for (int k = 0; k < 4; k++) acc[j][k] = 0.f;

        #pragma unroll
        for (int ks = 0; ks < 4; ks++) {
            #pragma unroll
            for (int nf = 0; nf < 2; nf++) {
                uint2 bf = *(const uint2*)(B + (wn * 16 + nf * 8 + g) * BROW_B
                                             + ks * 32 + 8 * t);
                mma_f16(acc[nf], a_lo[ks].x, a_hi[ks].x, a_lo[ks].y, a_hi[ks].y,
                        bf.x, bf.y);
            }
        }

        #pragma unroll
        for (int nf = 0; nf < 2; nf++) {
            float e0 = __expf(acc[nf][0]);
            float e1 = __expf(acc[nf][1]);
            float e2 = __expf(acc[nf][2]);
            float e3 = __expf(acc[nf][3]);
            rowsum0 += e0 + e1;
            rowsum1 += e2 + e3;
            int col2 = c * 32 + wn * 8 + nf * 4 + t;
            __half2 h0 = __floats2half2_rn(e0, e1);
            __half2 h1 = __floats2half2_rn(e2, e3);
            Eb[(size_t)(wm * 16 + g) * (V_ / 2) + col2] = *(unsigned*)&h0;
            Eb[(size_t)(wm * 16 + 8 + g) * (V_ / 2) + col2] = *(unsigned*)&h1;
        }
        __syncthreads();
    }

    // ---------------- row-sum reduction ----------------
    {
        float s0 = rowsum0, s1 = rowsum1;
        s0 += __shfl_xor_sync(0xffffffffu, s0, 1);
        s0 += __shfl_xor_sync(0xffffffffu, s0, 2);
        s1 += __shfl_xor_sync(0xffffffffu, s1, 1);
        s1 += __shfl_xor_sync(0xffffffffu, s1, 2);
        if (t == 0) {
            red[wn * 32 + wm * 16 + g] = s0;
            red[wn * 32 + wm * 16 + 8 + g] = s1;
        }
    }
    __syncthreads();
    if (tid < 32) {
        float s = red[tid] + red[32 + tid] + red[64 + tid] + red[96 + tid];
        invs[tid] = 1.0f / s;
    }
    __syncthreads();   // also orders pass-1 E stores before pass-2 loads (intra-CTA)

    // ---------------- PASS 2: read E (L2), scale, write G ----------------
    const int row = tid >> 3;            // 0..31
    const int c2b = tid & 7;
    const float iv = invs[row];
    float* grow = G + ((size_t)(nt * V_ + vbase + row)) * V_;
    const uint4* er = (const uint4*)(Eb + (size_t)row * (V_ / 2));
    #pragma unroll 4
    for (int j = 0; j < 16; j++) {
        uint4 u = er[c2b + 8 * j];       // 8 fp16 = cols 8*(c2b+8j) .. +7
        float2 f0 = __half22float2(*(__half2*)&u.x);
        float2 f1 = __half22float2(*(__half2*)&u.y);
        float2 f2 = __half22float2(*(__half2*)&u.z);
        float2 f3 = __half22float2(*(__half2*)&u.w);
        float4 o0 = make_float4(f0.x * iv, f0.y * iv, f1.x * iv, f1.y * iv);
        float4 o1 = make_float4(f2.x * iv, f2.y * iv, f3.x * iv, f3.y * iv);
        float* dst = grow + 8 * (c2b + 8 * j);
        *(float4*)dst = o0;
        *(float4*)(dst + 4) = o1;
    }
}

// ============================================================================
extern "C" void kernel_launch(void* const* d_in, const int* in_sizes, int n_in,
                              void* d_out, int out_size)
{
    const float* z  = (const float*)d_in[0];
    const float* tw = (const float*)d_in[1];
    const float* tb = (const float*)d_in[2];
    const float* pw = (const float*)d_in[3];
    const float* pb = (const float*)d_in[4];
    float* G = (float*)d_out;

    cudaFuncSetAttribute(proj_kernel, cudaFuncAttributeMaxDynamicSharedMemorySize,
                         PJ_SMEM_BYTES);
    proj_kernel<<<dim3(V_ / 128, NT_), 256, PJ_SMEM_BYTES>>>(z, tw, tb, pw, pb);

    cudaFuncSetAttribute(adj_kernel, cudaFuncAttributeMaxDynamicSharedMemorySize,
                         ADJ_SMEM_BYTES);
    adj_kernel<<<NT_ * 32, 256, ADJ_SMEM_BYTES>>>(G);
}

// round 17
// speedup vs baseline: 1.0915x; 1.0915x over previous
#include <cuda_runtime.h>
#include <cuda_fp16.h>
#include <cstdint>

// Problem constants
#define NT_   128      // N*T
#define V_    1024
#define CIN_  256
#define COUT_ 64

// Scratch: theta/phi projections, fp16, row-major [v][64] with k-permuted
// 16-groups => {2t,2t+1,2t+8,2t+9} contiguous: one 8B load per mma fragment.
__device__ __half g_theta[NT_ * V_ * COUT_];
__device__ __half g_phi[NT_ * V_ * COUT_];

// ---------------- tf32 mma (proj kernel) ----------------
__device__ __forceinline__ void mma_tf32(float* c,
                                         float a0, float a1, float a2, float a3,
                                         float b0, float b1) {
    asm volatile(
        "mma.sync.aligned.m16n8k8.row.col.f32.tf32.tf32.f32 "
        "{%0,%1,%2,%3},{%4,%5,%6,%7},{%8,%9},{%0,%1,%2,%3};\n"
        : "+f"(c[0]), "+f"(c[1]), "+f"(c[2]), "+f"(c[3])
        : "r"(__float_as_uint(a0)), "r"(__float_as_uint(a1)),
          "r"(__float_as_uint(a2)), "r"(__float_as_uint(a3)),
          "r"(__float_as_uint(b0)), "r"(__float_as_uint(b1)));
}

// ---------------- fp16 mma (adj kernel) ----------------
__device__ __forceinline__ void mma_f16(float* c,
                                        unsigned a0, unsigned a1,
                                        unsigned a2, unsigned a3,
                                        unsigned b0, unsigned b1) {
    asm volatile(
        "mma.sync.aligned.m16n8k16.row.col.f32.f16.f16.f32 "
        "{%0,%1,%2,%3},{%4,%5,%6,%7},{%8,%9},{%0,%1,%2,%3};\n"
        : "+f"(c[0]), "+f"(c[1]), "+f"(c[2]), "+f"(c[3])
        : "r"(a0), "r"(a1), "r"(a2), "r"(a3), "r"(b0), "r"(b1));
}

__device__ __forceinline__ uint32_t smem_u32(const void* p) {
    uint32_t a;
    asm("{ .reg .u64 t; cvta.to.shared.u64 t, %1; cvt.u32.u64 %0, t; }"
        : "=r"(a) : "l"(p));
    return a;
}
__device__ __forceinline__ void cp16s(uint32_t daddr, const void* src) {
    asm volatile("cp.async.cg.shared.global [%0], [%1], 16;\n" :: "r"(daddr), "l"(src));
}
__device__ __forceinline__ void cp_commit() { asm volatile("cp.async.commit_group;\n"); }
__device__ __forceinline__ void cp_wait0() { asm volatile("cp.async.wait_group 0;\n" ::: "memory"); }
__device__ __forceinline__ void cp_wait1() { asm volatile("cp.async.wait_group 1;\n" ::: "memory"); }

// ============================================================================
// Kernel 1: projection (unchanged from R12).
// Block: 128 v-rows x 128 out-cols, 256 thr, 2 CTAs/SM.
// ============================================================================
#define PJ_SR     40
#define PJ_A_SZ   (128 * PJ_SR)
#define PJ_BUF    (2 * PJ_A_SZ)
#define PJ_SMEM_BYTES (2 * PJ_BUF * 4)

__global__ void __launch_bounds__(256, 2) proj_kernel(
    const float* __restrict__ z, const float* __restrict__ tw,
    const float* __restrict__ tb, const float* __restrict__ pw,
    const float* __restrict__ pb)
{
    extern __shared__ float psm[];
    __shared__ float bias_s[128];

    const int tid = threadIdx.x, lane = tid & 31, wid = tid >> 5;
    const int g = lane >> 2, t = lane & 3;
    const int wm = wid & 3, wn = wid >> 2;
    const int nt = blockIdx.y;
    const int vbase = blockIdx.x * 128;

    if (tid < 128) bias_s[tid] = (tid < 64) ? tb[tid] : pb[tid - 64];

    const float* zb = z + (size_t)(nt * V_ + vbase) * CIN_;
    const uint32_t sb = smem_u32(psm);

    auto stage = [&](int c, int b) {
        const uint32_t ab = sb + (uint32_t)(b * PJ_BUF) * 4u;
        const uint32_t bb = ab + (uint32_t)PJ_A_SZ * 4u;
        const int kc = c * 32;
        #pragma unroll
        for (int p = 0; p < 4; p++) {
            int lin = tid + 256 * p;
            int r = lin >> 3, c8 = lin & 7;
            cp16s(ab + (uint32_t)(r * PJ_SR * 4 + c8 * 16),
                  zb + (size_t)r * CIN_ + kc + c8 * 4);
        }
        #pragma unroll
        for (int p = 0; p < 4; p++) {
            int lin = tid + 256 * p;
            int r = lin >> 3, c8 = lin & 7;
            const float* src = (r < 64) ? (tw + (size_t)r * CIN_)
                                        : (pw + (size_t)(r - 64) * CIN_);
            cp16s(bb + (uint32_t)(r * PJ_SR * 4 + c8 * 16), src + kc + c8 * 4);
        }
        cp_commit();
    };

    float acc[2][8][4];
    #pragma unroll
    for (int i = 0; i < 2; i++)
        #pragma unroll
        for (int j = 0; j < 8; j++)
            #pragma unroll
            for (int k = 0; k < 4; k++) acc[i][j][k] = 0.f;

    stage(0, 0);
    for (int c = 0; c < 8; c++) {
        if (c < 7) stage(c + 1, (c + 1) & 1);
        if (c < 7) cp_wait1(); else cp_wait0();
        __syncthreads();
        const float* A = psm + (c & 1) * PJ_BUF;
        const float* B = A + PJ_A_SZ;

        #pragma unroll
        for (int ks = 0; ks < 4; ks++) {
            const int ko = ks * 8 + 2 * t;
            float2 a0[2], a1[2];
            #pragma unroll
            for (int mf = 0; mf < 2; mf++) {
                a0[mf] = *(const float2*)&A[(wm * 32 + mf * 16 + g) * PJ_SR + ko];
                a1[mf] = *(const float2*)&A[(wm * 32 + mf * 16 + 8 + g) * PJ_SR + ko];
            }
            #pragma unroll
            for (int nf = 0; nf < 8; nf++) {
                float2 bf = *(const float2*)&B[(wn * 64 + nf * 8 + g) * PJ_SR + ko];
                #pragma unroll
                for (int mf = 0; mf < 2; mf++)
                    mma_tf32(acc[mf][nf], a0[mf].x, a1[mf].x, a0[mf].y, a1[mf].y,
                             bf.x, bf.y);
            }
        }
        __syncthreads();
    }

    // Epilogue: bias, convert to fp16, store at permuted k positions.
    __half* dst = wn ? g_phi : g_theta;
    #pragma unroll
    for (int mf = 0; mf < 2; mf++) {
        const size_t row0 = (size_t)(nt * V_) + vbase + wm * 32 + mf * 16 + g;
        #pragma unroll
        for (int nf = 0; nf < 8; nf++) {
            int c = nf * 8 + 2 * t;
            float b0 = bias_s[wn * 64 + c], b1 = bias_s[wn * 64 + c + 1];
            __half2 h0 = __floats2half2_rn(acc[mf][nf][0] + b0, acc[mf][nf][1] + b1);
            __half2 h1 = __floats2half2_rn(acc[mf][nf][2] + b0, acc[mf][nf][3] + b1);
            int h2i = (nf >> 1) * 8 + 2 * t + (nf & 1);
            *(__half2*)&dst[row0 * COUT_ + 2 * h2i] = h0;
            *(__half2*)&dst[(row0 + 8) * COUT_ + 2 * h2i] = h1;
        }
    }
}

// ============================================================================
// Kernel 2: fp16-HMMA softmax-GEMM with exp(S) held in REGISTERS.
// Block: 16 theta rows x 1024 cols, 256 thr (8 warps; all warps share the 16
// rows, warp wn owns cols wn*8 within each 64-col chunk). Per thread E share =
// 64 values = 32 half2 regs. No E buffer, no pass-2 loads. SMEM = phi double
// buffer only (20.6KB) -> 3 CTAs/SM (reg-limited), 24 warps.
// ============================================================================
#define BROW_B   160                       // bytes per phi row (128 data + 32 pad)
#define PBUF_B   (64 * BROW_B)             // 10240
#define ADJ_SMEM_BYTES (2 * PBUF_B)        // 20480

__global__ void __launch_bounds__(256, 3) adj_kernel(float* __restrict__ G)
{
    extern __shared__ char Pc[];              // 2 x 64 x BROW_B
    __shared__ float red[128];
    __shared__ float invs[16];

    const int tid = threadIdx.x, lane = tid & 31;
    const int wn = tid >> 5;     // 8 n-warps x 8 cols (per 64-col chunk)
    const int g = lane >> 2, t = lane & 3;
    const int nt = blockIdx.x >> 6;
    const int vbase = (blockIdx.x & 63) * 16;

    const __half* th = g_theta + (size_t)(nt * V_ + vbase) * COUT_;
    const __half* ph = g_phi + (size_t)nt * V_ * COUT_;
    const uint32_t pbb = smem_u32(Pc);

    // Theta fragments -> registers: rows g (lo) and 8+g (hi), one LDG.64 each.
    uint2 a_lo[4], a_hi[4];
    #pragma unroll
    for (int ks = 0; ks < 4; ks++) {
        a_lo[ks] = *(const uint2*)&th[(size_t)g * COUT_ + ks * 16 + 4 * t];
        a_hi[ks] = *(const uint2*)&th[(size_t)(8 + g) * COUT_ + ks * 16 + 4 * t];
    }

    auto stage = [&](int c, int b) {
        const uint32_t dst = pbb + (uint32_t)(b * PBUF_B);
        const __half* src = ph + (size_t)c * 64 * COUT_;
        #pragma unroll
        for (int p = 0; p < 2; p++) {
            int lin = tid + 256 * p;          // 0..511: 64 rows x 8 16B-chunks
            int r = lin >> 3, c8 = lin & 7;
            cp16s(dst + (uint32_t)(r * BROW_B + c8 * 16),
                  src + (size_t)r * COUT_ + c8 * 8);
        }
        cp_commit();
    };

    stage(0, 0);
    float rowsum0 = 0.f, rowsum1 = 0.f;
    unsigned Elo[16], Ehi[16];   // exp(S) fp16x2: [chunk] for rows g / 8+g

    // ---------------- mma -> exp -> regs + rowsums ----------------
    for (int c = 0; c < 16; c++) {
        if (c < 15) stage(c + 1, (c + 1) & 1);
        if (c < 15) cp_wait1(); else cp_wait0();
        __syncthreads();
        const char* B = Pc + (c & 1) * PBUF_B;

        float acc[4] = {0.f, 0.f, 0.f, 0.f};
        #pragma unroll
        for (int ks = 0; ks < 4; ks++) {
            uint2 bf = *(const uint2*)(B + (wn * 8 + g) * BROW_B + ks * 32 + 8 * t);
            mma_f16(acc, a_lo[ks].x, a_hi[ks].x, a_lo[ks].y, a_hi[ks].y,
                    bf.x, bf.y);
        }

        float e0 = __expf(acc[0]);
        float e1 = __expf(acc[1]);
        float e2 = __expf(acc[2]);
        float e3 = __expf(acc[3]);
        rowsum0 += e0 + e1;
        rowsum1 += e2 + e3;
        __half2 h0 = __floats2half2_rn(e0, e1);
        __half2 h1 = __floats2half2_rn(e2, e3);
        Elo[c] = *(unsigned*)&h0;
        Ehi[c] = *(unsigned*)&h1;
        __syncthreads();
    }

    // ---------------- row-sum reduction (16 rows, 8 warps) ----------------
    {
        float s0 = rowsum0, s1 = rowsum1;
        s0 += __shfl_xor_sync(0xffffffffu, s0, 1);
        s0 += __shfl_xor_sync(0xffffffffu, s0, 2);
        s1 += __shfl_xor_sync(0xffffffffu, s1, 1);
        s1 += __shfl_xor_sync(0xffffffffu, s1, 2);
        if (t == 0) {
            red[wn * 16 + g] = s0;
            red[wn * 16 + 8 + g] = s1;
        }
    }
    __syncthreads();
    if (tid < 16) {
        float s = 0.f;
        #pragma unroll
        for (int w = 0; w < 8; w++) s += red[w * 16 + tid];
        invs[tid] = 1.0f / s;
    }
    __syncthreads();

    // ---------------- scale from regs, write G ----------------
    const float iv0 = invs[g];
    const float iv1 = invs[8 + g];
    float* g0 = G + ((size_t)(nt * V_ + vbase + g)) * V_ + wn * 8 + 2 * t;
    float* g1 = G + ((size_t)(nt * V_ + vbase + 8 + g)) * V_ + wn * 8 + 2 * t;
    #pragma unroll
    for (int c = 0; c < 16; c++) {
        float2 f0 = __half22float2(*(__half2*)&Elo[c]);
        float2 f1 = __half22float2(*(__half2*)&Ehi[c]);
        *(float2*)(g0 + c * 64) = make_float2(f0.x * iv0, f0.y * iv0);
        *(float2*)(g1 + c * 64) = make_float2(f1.x * iv1, f1.y * iv1);
    }
}

// ============================================================================
extern "C" void kernel_launch(void* const* d_in, const int* in_sizes, int n_in,
                              void* d_out, int out_size)
{
    const float* z  = (const float*)d_in[0];
    const float* tw = (const float*)d_in[1];
    const float* tb = (const float*)d_in[2];
    const float* pw = (const float*)d_in[3];
    const float* pb = (const float*)d_in[4];
    float* G = (float*)d_out;

    cudaFuncSetAttribute(proj_kernel, cudaFuncAttributeMaxDynamicSharedMemorySize,
                         PJ_SMEM_BYTES);
    proj_kernel<<<dim3(V_ / 128, NT_), 256, PJ_SMEM_BYTES>>>(z, tw, tb, pw, pb);

    cudaFuncSetAttribute(adj_kernel, cudaFuncAttributeMaxDynamicSharedMemorySize,
                         ADJ_SMEM_BYTES);
    adj_kernel<<<NT_ * 64, 256, ADJ_SMEM_BYTES>>>(G);
}